// round 15
// baseline (speedup 1.0000x reference)
#include <cuda_runtime.h>
#include <cuda_fp16.h>
#include <cstdint>

#define N_ROWS 32768
#define D      64
#define K      1024
#define NTHR   256                     // 8 warps per CTA
#define ROWS_CTA 128
#define NRB    (N_ROWS / ROWS_CTA)     // 256 row-blocks
#define NBLK   (NRB * 2)               // 512 CTAs (split-K pairs)
#define NCH    64
#define NCHH   8                       // chunks per half (K/2/NCH)

#define OFF_QUANT 0
#define OFF_ENC   ((size_t)N_ROWS * D)
#define OFF_IDX   (OFF_ENC + (size_t)N_ROWS * K)
#define OFF_LOSS  (OFF_IDX + (size_t)N_ROWS)

// smem (floats): esq[1024] | buf0[3072] | buf1[3072] | xtile[128*68] | tabs[128] | tabi[128] | wl[16] | bc[4]
#define SMF_ESQ  0
#define SMF_BUF  1024
#define SMF_X    (1024 + 6144)
#define XSTRIDE  68
#define SMF_TABS (SMF_X + 128 * XSTRIDE)
#define SMF_TABI (SMF_TABS + 128)
#define SMF_WL   (SMF_TABI + 128)
#define SMF_BC   (SMF_WL + 16)
#define SMEM_SZ  ((SMF_BC + 4) * 4)              // 64592 B -> 3 CTAs/SM

// Packed per-chunk B block (12KB each, 16 chunks):
//   u4[  0..255]  hi ks0|ks1   [nt(8)][lane(32)] -> uint4
//   u4[256..511]  hi ks2|ks3
//   u2[1024..1279] esq hi (ks4 pseudo-dim)   (byte 8192)
//   u2[1280..1535] esq lo                    (byte 10240)
__device__ uint4 g_bpk[16 * 768];
__device__ float g_et [K * D];           // exact emb^T [k][d]
__device__ float g_esq[K];
__device__ unsigned long long g_half[2 * N_ROWS];  // packed (scorebits,idx)
__device__ unsigned int g_rbdone[NRB];   // wraps 0<->1 per launch
__device__ unsigned long long g_loss;
__device__ unsigned int g_done;          // wraps to 0 each launch (atomicInc)

__device__ __forceinline__ uint32_t smem_u32(const void* p) {
    uint32_t a;
    asm("{ .reg .u64 t; cvta.to.shared.u64 t, %1; cvt.u32.u64 %0, t; }"
        : "=r"(a) : "l"(p));
    return a;
}
__device__ __forceinline__ uint32_t packh2(float a, float b) {
    __half2 h = __floats2half2_rn(a, b);   // a -> low half (smaller index)
    return *(uint32_t*)&h;
}
// order-preserving float -> u32 (monotone for all finite values)
__device__ __forceinline__ uint32_t orderbits(float s) {
    uint32_t u = __float_as_uint(s);
    return (u & 0x80000000u) ? ~u : (u | 0x80000000u);
}

#define CP16(dst, src) asm volatile( \
    "cp.async.cg.shared.global [%0], [%1], 16;" :: "r"(dst), "l"(src) : "memory")
#define CP_COMMIT() asm volatile("cp.async.commit_group;" ::: "memory")
#define CP_WAIT0()  asm volatile("cp.async.wait_group 0;" ::: "memory")

#define LDS64(r0, r1, addr) asm volatile( \
    "ld.shared.v2.b32 {%0,%1}, [%2];" : "=r"(r0), "=r"(r1) : "r"(addr))
#define LDS128(r0, r1, r2, r3, addr) asm volatile( \
    "ld.shared.v4.b32 {%0,%1,%2,%3}, [%4];" \
    : "=r"(r0), "=r"(r1), "=r"(r2), "=r"(r3) : "r"(addr))

#define MMAF16(Cp, Ap, B0, B1) asm volatile( \
    "mma.sync.aligned.m16n8k16.row.col.f32.f16.f16.f32 " \
    "{%0,%1,%2,%3},{%4,%5,%6,%7},{%8,%9},{%0,%1,%2,%3};" \
    : "+f"((Cp)[0]), "+f"((Cp)[1]), "+f"((Cp)[2]), "+f"((Cp)[3]) \
    : "r"((Ap)[0]), "r"((Ap)[1]), "r"((Ap)[2]), "r"((Ap)[3]), \
      "r"(B0), "r"(B1))

// ---------------- prep: e^T, ||e||^2, packed fp16-hi fragments -------------
__global__ void prep_all(const float* __restrict__ emb) {
    int idx = blockIdx.x * blockDim.x + threadIdx.x;   // 0..4095
    if (idx == 0) g_loss = 0ull;
    int lane = idx & 31;
    int ntg  = idx >> 5;                 // 0..127 global n-tile
    int c    = ntg >> 3, nt = ntg & 7;
    int cw   = ntg * 8 + (lane >> 2);

    uint4 hi01, hi23;
    #pragma unroll
    for (int ks = 0; ks < 4; ks++) {
        int d0 = ks * 16 + (lane & 3) * 2;
        float v0 = emb[(d0    ) * K + cw];
        float v1 = emb[(d0 + 1) * K + cw];
        float v2 = emb[(d0 + 8) * K + cw];
        float v3 = emb[(d0 + 9) * K + cw];
        uint32_t hu0 = packh2(v0, v1), hu1 = packh2(v2, v3);
        if (ks == 0)      { hi01.x = hu0; hi01.y = hu1; }
        else if (ks == 1) { hi01.z = hu0; hi01.w = hu1; }
        else if (ks == 2) { hi23.x = hu0; hi23.y = hu1; }
        else              { hi23.z = hu0; hi23.w = hu1; }
    }
    int slot = c * 768 + nt * 32 + lane;
    g_bpk[slot      ] = hi01;
    g_bpk[slot + 256] = hi23;

    // ks4: esq pseudo-dim (hi+lo split -> exact); lane&3==0 carries data
    {
        uint2 hv = make_uint2(0, 0), lv = make_uint2(0, 0);
        if ((lane & 3) == 0) {
            float esq = 0.f;
            #pragma unroll
            for (int d = 0; d < D; d++) {
                float v = emb[d * K + cw];
                esq = fmaf(v, v, esq);
            }
            float eh = __half2float(__float2half_rn(esq));
            hv.x = packh2(eh, 0.f);
            lv.x = packh2(esq - eh, 0.f);
        }
        uint2* p2 = (uint2*)g_bpk;
        p2[c * 1536 + 1024 + nt * 32 + lane] = hv;
        p2[c * 1536 + 1280 + nt * 32 + lane] = lv;
    }
    // exact transpose + norms (first 1024 threads)
    if (idx < K) {
        float s = 0.f;
        #pragma unroll
        for (int d = 0; d < D; d++) {
            float v = emb[d * K + idx];
            g_et[idx * D + d] = v;
            s = fmaf(v, v, s);
        }
        g_esq[idx] = s;
    }
}

// ---------------- staging: 12KB linear copy per chunk ----------------------
__device__ __forceinline__ void stage_chunk(uint32_t bufb, int c, int tid) {
    const char* s = (const char*)(g_bpk + (size_t)c * 768);
    #pragma unroll
    for (int i = 0; i < 3; i++) {
        uint32_t o = (uint32_t)(i * NTHR + tid) * 16;
        CP16(bufb + o, s + o);
    }
    CP_COMMIT();
}

__device__ __forceinline__ bool sless(float s, int i, float S, int I) {
    return (s < S) || (s == S && i < I);
}

// exact fp32 score of codeword k against x row in smem
__device__ __forceinline__ float exact_score(const float4* __restrict__ xp,
                                             int k, const float* esq_s) {
    const float4* ep = (const float4*)(g_et + (size_t)k * D);
    float d0 = 0.f;
    #pragma unroll
    for (int i = 0; i < 16; i++) {
        float4 xv = xp[i], ev = ep[i];
        d0 = fmaf(xv.x, ev.x, d0); d0 = fmaf(xv.y, ev.y, d0);
        d0 = fmaf(xv.z, ev.z, d0); d0 = fmaf(xv.w, ev.w, d0);
    }
    return fmaf(-2.f, d0, esq_s[k]);
}

// ---------------- main ------------------------------------------------------
__global__ __launch_bounds__(NTHR, 3) void vq_mma(const float* __restrict__ x,
                                                  float* __restrict__ out) {
    extern __shared__ __align__(16) float smem[];
    const uint32_t smb = smem_u32(smem);
    float* esq_s = smem + SMF_ESQ;
    float* xs    = smem + SMF_X;
    const int tid  = threadIdx.x;
    const int wid  = tid >> 5, lane = tid & 31;
    const int r0   = lane >> 2, c0 = lane & 3;
    const int rb   = blockIdx.x >> 1;        // row-block
    const int h    = blockIdx.x & 1;         // codebook half
    const int rowbase = rb * ROWS_CTA;

    stage_chunk(smb + SMF_BUF * 4, h * NCHH, tid);

    #pragma unroll
    for (int i = 0; i < K / NTHR; i++)
        esq_s[i * NTHR + tid] = g_esq[i * NTHR + tid];

    // stage x tile (raw floats, stride 68 => conflict-free row reads)
    {
        const float4* xg = (const float4*)(x + (size_t)rowbase * D);
        #pragma unroll
        for (int i = 0; i < 8; i++) {
            int idx = i * NTHR + tid;
            int r = idx >> 4, d4 = idx & 15;
            *(float4*)(xs + r * XSTRIDE + d4 * 4) = xg[idx];
        }
    }
    __syncthreads();

    // A fragments: y = fp16(-2x), single term; +ks4 pseudo-dim (y=1).
    uint32_t ay0[20];
    #pragma unroll
    for (int ks = 0; ks < 4; ks++)
        #pragma unroll
        for (int p = 0; p < 4; p++) {
            int r = wid * 16 + r0 + (p & 1) * 8;
            int d = ks * 16 + c0 * 2 + (p >> 1) * 8;
            ay0[ks * 4 + p] = packh2(-2.f * xs[r * XSTRIDE + d],
                                     -2.f * xs[r * XSTRIDE + d + 1]);
        }
    {
        uint32_t one = (c0 == 0) ? packh2(1.f, 0.f) : 0u;
        ay0[16] = one; ay0[17] = one; ay0[18] = 0u; ay0[19] = 0u;
    }

    // per-slot approx top-2; slot 0 = row r0, slot 1 = row r0+8
    float s1[2], s2[2];
    int   i1[2], i2[2];
    #pragma unroll
    for (int s = 0; s < 2; s++) {
        s1[s] = s2[s] = 3.4e38f; i1[s] = i2[s] = h * (K / 2);
    }

    #pragma unroll 1
    for (int cc = 0; cc < NCHH; cc++) {
        const int c = h * NCHH + cc;         // global chunk
        CP_WAIT0();
        __syncthreads();   // buf[cc] visible; prior reads of other buf done
        if (cc + 1 < NCHH)
            stage_chunk(smb + (SMF_BUF + ((cc + 1) & 1) * 3072) * 4,
                        c + 1, tid);

        // encodings zero-fill for this chunk's 64 columns
        {
            float4 z = make_float4(0.f, 0.f, 0.f, 0.f);
            float* enc = out + OFF_ENC + (size_t)rowbase * K + (size_t)c * NCH;
            #pragma unroll
            for (int j = 0; j < 8; j++) {
                int idx = j * NTHR + tid;
                *(float4*)(enc + (size_t)(idx >> 4) * K + (idx & 15) * 4) = z;
            }
        }

        const uint32_t bufb = smb + (SMF_BUF + (cc & 1) * 3072) * 4;

        // nt pairs: two independent accumulator chains
        #pragma unroll
        for (int nt = 0; nt < 8; nt += 2) {
            uint32_t Ah01[4], Ah23[4], Ah4[2], Al4[2];
            uint32_t Bh01[4], Bh23[4], Bh4[2], Bl4[2];
            {
                uint32_t a16 = bufb + (uint32_t)(((nt    ) * 32 + lane) * 16);
                uint32_t b16 = bufb + (uint32_t)(((nt + 1) * 32 + lane) * 16);
                uint32_t a8  = bufb + (uint32_t)(((nt    ) * 32 + lane) * 8);
                uint32_t b8  = bufb + (uint32_t)(((nt + 1) * 32 + lane) * 8);
                LDS128(Ah01[0], Ah01[1], Ah01[2], Ah01[3], a16);
                LDS128(Bh01[0], Bh01[1], Bh01[2], Bh01[3], b16);
                LDS128(Ah23[0], Ah23[1], Ah23[2], Ah23[3], a16 + 4096);
                LDS128(Bh23[0], Bh23[1], Bh23[2], Bh23[3], b16 + 4096);
                LDS64(Ah4[0], Ah4[1], a8 + 8192);
                LDS64(Bh4[0], Bh4[1], b8 + 8192);
                LDS64(Al4[0], Al4[1], a8 + 10240);
                LDS64(Bl4[0], Bl4[1], b8 + 10240);
            }
            float C0[4] = {0.f, 0.f, 0.f, 0.f};
            float C1[4] = {0.f, 0.f, 0.f, 0.f};
            MMAF16(C0, ay0 + 0,  Ah01[0], Ah01[1]);   // ks0
            MMAF16(C1, ay0 + 0,  Bh01[0], Bh01[1]);
            MMAF16(C0, ay0 + 4,  Ah01[2], Ah01[3]);   // ks1
            MMAF16(C1, ay0 + 4,  Bh01[2], Bh01[3]);
            MMAF16(C0, ay0 + 8,  Ah23[0], Ah23[1]);   // ks2
            MMAF16(C1, ay0 + 8,  Bh23[0], Bh23[1]);
            MMAF16(C0, ay0 + 12, Ah23[2], Ah23[3]);   // ks3
            MMAF16(C1, ay0 + 12, Bh23[2], Bh23[3]);
            MMAF16(C0, ay0 + 16, Ah4[0],  Ah4[1]);    // ks4 esq hi
            MMAF16(C1, ay0 + 16, Bh4[0],  Bh4[1]);
            MMAF16(C0, ay0 + 16, Al4[0],  Al4[1]);    // ks4 esq lo
            MMAF16(C1, ay0 + 16, Bl4[0],  Bl4[1]);

            // approx pair-then-insert top-2 (cols ascending, strict <)
            int cbA = c * NCH + nt * 8 + c0 * 2;
            int cbB = cbA + 8;
            {
                float m = fminf(C0[0], C0[1]);
                int  mc = cbA + ((C0[1] < C0[0]) ? 1 : 0);
                bool p1 = m < s1[0], p2 = m < s2[0];
                s2[0] = p1 ? s1[0] : (p2 ? m : s2[0]);
                i2[0] = p1 ? i1[0] : (p2 ? mc : i2[0]);
                i1[0] = p1 ? mc : i1[0];
                s1[0] = p1 ? m  : s1[0];
            }
            {
                float m = fminf(C0[2], C0[3]);
                int  mc = cbA + ((C0[3] < C0[2]) ? 1 : 0);
                bool p1 = m < s1[1], p2 = m < s2[1];
                s2[1] = p1 ? s1[1] : (p2 ? m : s2[1]);
                i2[1] = p1 ? i1[1] : (p2 ? mc : i2[1]);
                i1[1] = p1 ? mc : i1[1];
                s1[1] = p1 ? m  : s1[1];
            }
            {
                float m = fminf(C1[0], C1[1]);
                int  mc = cbB + ((C1[1] < C1[0]) ? 1 : 0);
                bool p1 = m < s1[0], p2 = m < s2[0];
                s2[0] = p1 ? s1[0] : (p2 ? m : s2[0]);
                i2[0] = p1 ? i1[0] : (p2 ? mc : i2[0]);
                i1[0] = p1 ? mc : i1[0];
                s1[0] = p1 ? m  : s1[0];
            }
            {
                float m = fminf(C1[2], C1[3]);
                int  mc = cbB + ((C1[3] < C1[2]) ? 1 : 0);
                bool p1 = m < s1[1], p2 = m < s2[1];
                s2[1] = p1 ? s1[1] : (p2 ? m : s2[1]);
                i2[1] = p1 ? i1[1] : (p2 ? mc : i2[1]);
                i1[1] = p1 ? mc : i1[1];
                s1[1] = p1 ? m  : s1[1];
            }
        }
    }

    // ---- exact rescue: rescore BOTH per-lane candidates, then quad-merge ----
    float* tabs = smem + SMF_TABS;
    int*   tabi = (int*)(smem + SMF_TABI);
    #pragma unroll
    for (int sl = 0; sl < 2; sl++) {
        int r = wid * 16 + sl * 8 + r0;
        const float4* xp = (const float4*)(xs + r * XSTRIDE);
        float ea = exact_score(xp, i1[sl], esq_s);
        float eb = exact_score(xp, i2[sl], esq_s);
        float bs; int bidx;
        if (sless(eb, i2[sl], ea, i1[sl])) { bs = eb; bidx = i2[sl]; }
        else                               { bs = ea; bidx = i1[sl]; }
        #pragma unroll
        for (int off = 1; off <= 2; off <<= 1) {
            float os = __shfl_xor_sync(0xFFFFFFFF, bs, off);
            int   oi = __shfl_xor_sync(0xFFFFFFFF, bidx, off);
            if (sless(os, oi, bs, bidx)) { bs = os; bidx = oi; }
        }
        if (c0 == 0) { tabs[r] = bs; tabi[r] = bidx; }
    }
    __syncthreads();

    // ---- publish this half's per-row result; second CTA merges ------------
    unsigned int* bc = (unsigned int*)(smem + SMF_BC);
    if (tid < ROWS_CTA) {
        unsigned long long key =
            ((unsigned long long)orderbits(tabs[tid]) << 32)
            | (unsigned int)tabi[tid];
        g_half[(size_t)h * N_ROWS + rowbase + tid] = key;
    }
    __syncthreads();
    if (tid == 0) {
        __threadfence();
        bc[0] = atomicInc(&g_rbdone[rb], 1);   // 0 = first, 1 = second
    }
    __syncthreads();
    if (bc[0] == 0) return;   // first CTA of the pair: done

    // ---- finisher: merge halves, write outputs + loss ----------------------
    long long* wl = (long long*)(smem + SMF_WL);
    if (tid < ROWS_CTA) {
        const int row = rowbase + tid;
        unsigned long long mykey =
            ((unsigned long long)orderbits(tabs[tid]) << 32)
            | (unsigned int)tabi[tid];
        unsigned long long okey = g_half[(size_t)(1 - h) * N_ROWS + row];
        unsigned long long mk = (okey < mykey) ? okey : mykey;
        const int bi = (int)(mk & 0xFFFFFFFFu);

        const float4* xp = (const float4*)(xs + tid * XSTRIDE);
        float ls = 0.f;
        {
            const float4* ep = (const float4*)(g_et + (size_t)bi * D);
            float4* qp = (float4*)(out + OFF_QUANT + (size_t)row * D);
            #pragma unroll
            for (int i = 0; i < 16; i++) {
                float4 e = ep[i], xv = xp[i];
                qp[i] = e;
                float a0 = e.x - xv.x, a1 = e.y - xv.y;
                float a2 = e.z - xv.z, a3 = e.w - xv.w;
                ls = fmaf(a0, a0, ls); ls = fmaf(a1, a1, ls);
                ls = fmaf(a2, a2, ls); ls = fmaf(a3, a3, ls);
            }
        }
        #pragma unroll
        for (int off = 16; off > 0; off >>= 1)
            ls += __shfl_xor_sync(0xFFFFFFFF, ls, off);
        if (lane == 0)   // fixed-point warp partial -> smem (deterministic)
            wl[wid] = (long long)__float2ll_rn(ls * 16777216.0f);

        out[OFF_IDX + row] = (float)bi;
        out[OFF_ENC + (size_t)row * K + bi] = 1.0f;
    }
    __syncthreads();

    // tid 0: single fenced g_loss add, then last-finisher loss write
    if (tid == 0) {
        long long csum = wl[0] + wl[1] + wl[2] + wl[3];
        atomicAdd(&g_loss, (unsigned long long)csum);
        __threadfence();
        unsigned int old = atomicInc(&g_done, NRB - 1);
        if (old == NRB - 1) {
            unsigned long long tot = atomicAdd(&g_loss, 0ull);
            out[OFF_LOSS] = (float)((double)tot
                          / (16777216.0 * (double)N_ROWS * (double)D));
        }
    }
}

extern "C" void kernel_launch(void* const* d_in, const int* in_sizes, int n_in,
                              void* d_out, int out_size) {
    const float* x   = (const float*)d_in[0];   // [8,4096,64]
    const float* emb = (const float*)d_in[1];   // [64,1024]
    float* out = (float*)d_out;

    cudaFuncSetAttribute(vq_mma, cudaFuncAttributeMaxDynamicSharedMemorySize,
                         SMEM_SZ);
    prep_all<<<16, 256>>>(emb);
    vq_mma<<<NBLK, NTHR, SMEM_SZ>>>(x, out);
}

// round 16
// speedup vs baseline: 1.2676x; 1.2676x over previous
#include <cuda_runtime.h>
#include <cuda_fp16.h>
#include <cstdint>

#define N_ROWS 32768
#define D      64
#define K      1024
#define NTHR   256                     // 8 warps per CTA
#define ROWS_CTA 128
#define NBLK   (N_ROWS / ROWS_CTA)     // 256 CTAs (2/SM -> one wave)
#define NBCH   8                       // big chunks (128 cw each)

#define OFF_QUANT 0
#define OFF_ENC   ((size_t)N_ROWS * D)
#define OFF_IDX   (OFF_ENC + (size_t)N_ROWS * K)
#define OFF_LOSS  (OFF_IDX + (size_t)N_ROWS)

// smem (floats): esq[1024] | buf0[6144] | buf1[6144] | xtile[128*68] | tab[128] | wl[16]
#define SMF_ESQ  0
#define SMF_BUF  1024
#define SMF_X    (1024 + 12288)
#define XSTRIDE  68
#define SMF_TAB  (SMF_X + 128 * XSTRIDE)
#define SMF_WL   (SMF_TAB + 128)
#define SMEM_SZ  ((SMF_WL + 16) * 4)             // 88640 B -> 2 CTAs/SM

// Packed per-64cw block (12KB each, 16 blocks; big chunk = 2 blocks = 24KB):
//   u4[  0..255]  hi ks0|ks1   [nt(8)][lane(32)] -> uint4
//   u4[256..511]  hi ks2|ks3
//   u2[1024..1279] esq hi (ks4 pseudo-dim)   (byte 8192)
//   u2[1280..1535] esq lo                    (byte 10240)
__device__ uint4 g_bpk[16 * 768];
__device__ float g_et [K * D];           // exact emb^T [k][d]
__device__ float g_esq[K];
__device__ unsigned long long g_loss;
__device__ unsigned int g_done;          // wraps to 0 each launch (atomicInc)

__device__ __forceinline__ uint32_t smem_u32(const void* p) {
    uint32_t a;
    asm("{ .reg .u64 t; cvta.to.shared.u64 t, %1; cvt.u32.u64 %0, t; }"
        : "=r"(a) : "l"(p));
    return a;
}
__device__ __forceinline__ uint32_t packh2(float a, float b) {
    __half2 h = __floats2half2_rn(a, b);   // a -> low half (smaller index)
    return *(uint32_t*)&h;
}

#define CP16(dst, src) asm volatile( \
    "cp.async.cg.shared.global [%0], [%1], 16;" :: "r"(dst), "l"(src) : "memory")
#define CP_COMMIT() asm volatile("cp.async.commit_group;" ::: "memory")
#define CP_WAIT0()  asm volatile("cp.async.wait_group 0;" ::: "memory")

#define LDS64(r0, r1, addr) asm volatile( \
    "ld.shared.v2.b32 {%0,%1}, [%2];" : "=r"(r0), "=r"(r1) : "r"(addr))
#define LDS128(r0, r1, r2, r3, addr) asm volatile( \
    "ld.shared.v4.b32 {%0,%1,%2,%3}, [%4];" \
    : "=r"(r0), "=r"(r1), "=r"(r2), "=r"(r3) : "r"(addr))

#define MMAF16(Cp, Ap, B0, B1) asm volatile( \
    "mma.sync.aligned.m16n8k16.row.col.f32.f16.f16.f32 " \
    "{%0,%1,%2,%3},{%4,%5,%6,%7},{%8,%9},{%0,%1,%2,%3};" \
    : "+f"((Cp)[0]), "+f"((Cp)[1]), "+f"((Cp)[2]), "+f"((Cp)[3]) \
    : "r"((Ap)[0]), "r"((Ap)[1]), "r"((Ap)[2]), "r"((Ap)[3]), \
      "r"(B0), "r"(B1))

// ---------------- prep: e^T, ||e||^2, packed fp16-hi fragments -------------
// 16 blocks x 256 threads; block b handles codewords [b*64, b*64+64).
// emb slice is staged into smem COALESCED, packing reads smem.
__global__ void prep_all(const float* __restrict__ emb) {
    __shared__ float es[64 * 65];        // [d][cw_local], stride 65 (bank-split)
    const int tid = threadIdx.x;
    const int idx = blockIdx.x * 256 + tid;
    if (idx == 0) g_loss = 0ull;
    const int cwbase = blockIdx.x * 64;

    // coalesced stage: 64-float segments
    #pragma unroll
    for (int i = 0; i < 16; i++) {
        int d = i * 4 + (tid >> 6);
        int j = tid & 63;
        es[d * 65 + j] = emb[d * K + cwbase + j];
    }
    __syncthreads();

    const int lane = tid & 31;
    const int nt   = tid >> 5;           // 0..7 (local n-tile)
    const int c    = blockIdx.x;         // 64cw block index
    const int cwl  = nt * 8 + (lane >> 2);   // local codeword 0..63

    uint4 hi01, hi23;
    #pragma unroll
    for (int ks = 0; ks < 4; ks++) {
        int d0 = ks * 16 + (lane & 3) * 2;
        float v0 = es[(d0    ) * 65 + cwl];
        float v1 = es[(d0 + 1) * 65 + cwl];
        float v2 = es[(d0 + 8) * 65 + cwl];
        float v3 = es[(d0 + 9) * 65 + cwl];
        uint32_t hu0 = packh2(v0, v1), hu1 = packh2(v2, v3);
        if (ks == 0)      { hi01.x = hu0; hi01.y = hu1; }
        else if (ks == 1) { hi01.z = hu0; hi01.w = hu1; }
        else if (ks == 2) { hi23.x = hu0; hi23.y = hu1; }
        else              { hi23.z = hu0; hi23.w = hu1; }
    }
    int slot = c * 768 + nt * 32 + lane;
    g_bpk[slot      ] = hi01;
    g_bpk[slot + 256] = hi23;

    // ks4: esq pseudo-dim (hi+lo split -> exact); lane&3==0 carries data
    {
        uint2 hv = make_uint2(0, 0), lv = make_uint2(0, 0);
        if ((lane & 3) == 0) {
            float esq = 0.f;
            #pragma unroll
            for (int d = 0; d < D; d++) {
                float v = es[d * 65 + cwl];
                esq = fmaf(v, v, esq);
            }
            float eh = __half2float(__float2half_rn(esq));
            hv.x = packh2(eh, 0.f);
            lv.x = packh2(esq - eh, 0.f);
            g_esq[cwbase + cwl] = esq;
        }
        uint2* p2 = (uint2*)g_bpk;
        p2[c * 1536 + 1024 + nt * 32 + lane] = hv;
        p2[c * 1536 + 1280 + nt * 32 + lane] = lv;
    }

    // exact transpose: 64 cw per block, each of first 64 threads owns one cw
    if (tid < 64) {
        int cw = cwbase + tid;
        float4* dst = (float4*)(g_et + (size_t)cw * D);
        #pragma unroll
        for (int i = 0; i < 16; i++) {
            dst[i] = make_float4(es[(4 * i    ) * 65 + tid],
                                 es[(4 * i + 1) * 65 + tid],
                                 es[(4 * i + 2) * 65 + tid],
                                 es[(4 * i + 3) * 65 + tid]);
        }
    }
}

// ---------------- staging: 24KB linear copy per big chunk ------------------
__device__ __forceinline__ void stage_chunk(uint32_t bufb, int c, int tid) {
    const char* s = (const char*)(g_bpk + (size_t)c * 1536);
    #pragma unroll
    for (int i = 0; i < 6; i++) {
        uint32_t o = (uint32_t)(i * NTHR + tid) * 16;
        CP16(bufb + o, s + o);
    }
    CP_COMMIT();
}

__device__ __forceinline__ bool sless(float s, int i, float S, int I) {
    return (s < S) || (s == S && i < I);
}

// exact fp32 score of codeword k against x row in smem
__device__ __forceinline__ float exact_score(const float4* __restrict__ xp,
                                             int k, const float* esq_s) {
    const float4* ep = (const float4*)(g_et + (size_t)k * D);
    float d0 = 0.f;
    #pragma unroll
    for (int i = 0; i < 16; i++) {
        float4 xv = xp[i], ev = ep[i];
        d0 = fmaf(xv.x, ev.x, d0); d0 = fmaf(xv.y, ev.y, d0);
        d0 = fmaf(xv.z, ev.z, d0); d0 = fmaf(xv.w, ev.w, d0);
    }
    return fmaf(-2.f, d0, esq_s[k]);
}

// ---------------- main ------------------------------------------------------
__global__ __launch_bounds__(NTHR, 2) void vq_mma(const float* __restrict__ x,
                                                  float* __restrict__ out) {
    extern __shared__ __align__(16) float smem[];
    const uint32_t smb = smem_u32(smem);
    float* esq_s = smem + SMF_ESQ;
    float* xs    = smem + SMF_X;
    const int tid  = threadIdx.x;
    const int wid  = tid >> 5, lane = tid & 31;
    const int r0   = lane >> 2, c0 = lane & 3;
    const int rowbase = blockIdx.x * ROWS_CTA;

    stage_chunk(smb + SMF_BUF * 4, 0, tid);

    #pragma unroll
    for (int i = 0; i < K / NTHR; i++)
        esq_s[i * NTHR + tid] = g_esq[i * NTHR + tid];

    // stage x tile (raw floats, stride 68 => conflict-free row reads)
    {
        const float4* xg = (const float4*)(x + (size_t)rowbase * D);
        #pragma unroll
        for (int i = 0; i < 8; i++) {
            int idx = i * NTHR + tid;
            int r = idx >> 4, d4 = idx & 15;
            *(float4*)(xs + r * XSTRIDE + d4 * 4) = xg[idx];
        }
    }
    __syncthreads();

    // A fragments: y = -2x, split y = y0 + y1 (fp16); +ks4 pseudo-dim (y=1).
    uint32_t ay0[20], ay1[16];
    #pragma unroll
    for (int ks = 0; ks < 4; ks++)
        #pragma unroll
        for (int p = 0; p < 4; p++) {
            int r = wid * 16 + r0 + (p & 1) * 8;
            int d = ks * 16 + c0 * 2 + (p >> 1) * 8;
            float va = -2.f * xs[r * XSTRIDE + d];
            float vb = -2.f * xs[r * XSTRIDE + d + 1];
            float ha = __half2float(__float2half_rn(va));
            float hb = __half2float(__float2half_rn(vb));
            ay0[ks * 4 + p] = packh2(ha, hb);
            ay1[ks * 4 + p] = packh2(va - ha, vb - hb);
        }
    {
        uint32_t one = (c0 == 0) ? packh2(1.f, 0.f) : 0u;
        ay0[16] = one; ay0[17] = one; ay0[18] = 0u; ay0[19] = 0u;
    }

    // per-slot approx top-2; slot 0 = row r0, slot 1 = row r0+8
    float s1[2], s2[2];
    int   i1[2], i2[2];
    #pragma unroll
    for (int s = 0; s < 2; s++) { s1[s] = s2[s] = 3.4e38f; i1[s] = i2[s] = 0; }

    #pragma unroll 1
    for (int c = 0; c < NBCH; c++) {
        CP_WAIT0();
        __syncthreads();   // buf[c] visible; prior reads of other buf done
        if (c + 1 < NBCH)
            stage_chunk(smb + (SMF_BUF + ((c + 1) & 1) * 6144) * 4, c + 1, tid);

        // encodings zero-fill for this big chunk's 128 columns
        {
            float4 z = make_float4(0.f, 0.f, 0.f, 0.f);
            float* enc = out + OFF_ENC + (size_t)rowbase * K + (size_t)c * 128;
            #pragma unroll
            for (int j = 0; j < 16; j++) {
                int idx = j * NTHR + tid;
                *(float4*)(enc + (size_t)(idx >> 5) * K + (idx & 31) * 4) = z;
            }
        }

        // two 64-cw sub-blocks per staged chunk
        #pragma unroll
        for (int sub = 0; sub < 2; sub++) {
            const uint32_t bufb = smb + (SMF_BUF + (c & 1) * 6144
                                         + sub * 3072) * 4;
            const int colchunk = c * 2 + sub;

            #pragma unroll
            for (int nt = 0; nt < 8; nt += 2) {
                uint32_t Ah01[4], Ah23[4], Ah4[2], Al4[2];
                uint32_t Bh01[4], Bh23[4], Bh4[2], Bl4[2];
                {
                    uint32_t a16 = bufb + (uint32_t)(((nt    ) * 32 + lane) * 16);
                    uint32_t b16 = bufb + (uint32_t)(((nt + 1) * 32 + lane) * 16);
                    uint32_t a8  = bufb + (uint32_t)(((nt    ) * 32 + lane) * 8);
                    uint32_t b8  = bufb + (uint32_t)(((nt + 1) * 32 + lane) * 8);
                    LDS128(Ah01[0], Ah01[1], Ah01[2], Ah01[3], a16);
                    LDS128(Bh01[0], Bh01[1], Bh01[2], Bh01[3], b16);
                    LDS128(Ah23[0], Ah23[1], Ah23[2], Ah23[3], a16 + 4096);
                    LDS128(Bh23[0], Bh23[1], Bh23[2], Bh23[3], b16 + 4096);
                    LDS64(Ah4[0], Ah4[1], a8 + 8192);
                    LDS64(Bh4[0], Bh4[1], b8 + 8192);
                    LDS64(Al4[0], Al4[1], a8 + 10240);
                    LDS64(Bl4[0], Bl4[1], b8 + 10240);
                }
                float C0[4] = {0.f, 0.f, 0.f, 0.f};
                float C1[4] = {0.f, 0.f, 0.f, 0.f};
                MMAF16(C0, ay0 + 0,  Ah01[0], Ah01[1]);   // ks0
                MMAF16(C1, ay0 + 0,  Bh01[0], Bh01[1]);
                MMAF16(C0, ay1 + 0,  Ah01[0], Ah01[1]);
                MMAF16(C1, ay1 + 0,  Bh01[0], Bh01[1]);
                MMAF16(C0, ay0 + 4,  Ah01[2], Ah01[3]);   // ks1
                MMAF16(C1, ay0 + 4,  Bh01[2], Bh01[3]);
                MMAF16(C0, ay1 + 4,  Ah01[2], Ah01[3]);
                MMAF16(C1, ay1 + 4,  Bh01[2], Bh01[3]);
                MMAF16(C0, ay0 + 8,  Ah23[0], Ah23[1]);   // ks2
                MMAF16(C1, ay0 + 8,  Bh23[0], Bh23[1]);
                MMAF16(C0, ay1 + 8,  Ah23[0], Ah23[1]);
                MMAF16(C1, ay1 + 8,  Bh23[0], Bh23[1]);
                MMAF16(C0, ay0 + 12, Ah23[2], Ah23[3]);   // ks3
                MMAF16(C1, ay0 + 12, Bh23[2], Bh23[3]);
                MMAF16(C0, ay1 + 12, Ah23[2], Ah23[3]);
                MMAF16(C1, ay1 + 12, Bh23[2], Bh23[3]);
                MMAF16(C0, ay0 + 16, Ah4[0],  Ah4[1]);    // ks4 esq hi
                MMAF16(C1, ay0 + 16, Bh4[0],  Bh4[1]);
                MMAF16(C0, ay0 + 16, Al4[0],  Al4[1]);    // ks4 esq lo
                MMAF16(C1, ay0 + 16, Bl4[0],  Bl4[1]);

                // approx pair-then-insert top-2 (cols ascending, strict <)
                int cbA = colchunk * 64 + nt * 8 + c0 * 2;
                int cbB = cbA + 8;
                {
                    float m = fminf(C0[0], C0[1]);
                    int  mc = cbA + ((C0[1] < C0[0]) ? 1 : 0);
                    bool p1 = m < s1[0], p2 = m < s2[0];
                    s2[0] = p1 ? s1[0] : (p2 ? m : s2[0]);
                    i2[0] = p1 ? i1[0] : (p2 ? mc : i2[0]);
                    i1[0] = p1 ? mc : i1[0];
                    s1[0] = p1 ? m  : s1[0];
                }
                {
                    float m = fminf(C0[2], C0[3]);
                    int  mc = cbA + ((C0[3] < C0[2]) ? 1 : 0);
                    bool p1 = m < s1[1], p2 = m < s2[1];
                    s2[1] = p1 ? s1[1] : (p2 ? m : s2[1]);
                    i2[1] = p1 ? i1[1] : (p2 ? mc : i2[1]);
                    i1[1] = p1 ? mc : i1[1];
                    s1[1] = p1 ? m  : s1[1];
                }
                {
                    float m = fminf(C1[0], C1[1]);
                    int  mc = cbB + ((C1[1] < C1[0]) ? 1 : 0);
                    bool p1 = m < s1[0], p2 = m < s2[0];
                    s2[0] = p1 ? s1[0] : (p2 ? m : s2[0]);
                    i2[0] = p1 ? i1[0] : (p2 ? mc : i2[0]);
                    i1[0] = p1 ? mc : i1[0];
                    s1[0] = p1 ? m  : s1[0];
                }
                {
                    float m = fminf(C1[2], C1[3]);
                    int  mc = cbB + ((C1[3] < C1[2]) ? 1 : 0);
                    bool p1 = m < s1[1], p2 = m < s2[1];
                    s2[1] = p1 ? s1[1] : (p2 ? m : s2[1]);
                    i2[1] = p1 ? i1[1] : (p2 ? mc : i2[1]);
                    i1[1] = p1 ? mc : i1[1];
                    s1[1] = p1 ? m  : s1[1];
                }
            }
        }
    }

    // ---- exact rescue: rescore BOTH per-lane candidates, then quad-merge ----
    int* rowtab = (int*)(smem + SMF_TAB);
    #pragma unroll
    for (int sl = 0; sl < 2; sl++) {
        int r = wid * 16 + sl * 8 + r0;
        const float4* xp = (const float4*)(xs + r * XSTRIDE);
        float ea = exact_score(xp, i1[sl], esq_s);
        float eb = exact_score(xp, i2[sl], esq_s);
        float bs; int bidx;
        if (sless(eb, i2[sl], ea, i1[sl])) { bs = eb; bidx = i2[sl]; }
        else                               { bs = ea; bidx = i1[sl]; }
        #pragma unroll
        for (int off = 1; off <= 2; off <<= 1) {
            float os = __shfl_xor_sync(0xFFFFFFFF, bs, off);
            int   oi = __shfl_xor_sync(0xFFFFFFFF, bidx, off);
            if (sless(os, oi, bs, bidx)) { bs = os; bidx = oi; }
        }
        if (c0 == 0) rowtab[r] = bidx;
    }
    __syncthreads();

    // final per-row epilogue (threads 0..127): outputs + loss
    long long* wl = (long long*)(smem + SMF_WL);
    if (tid < ROWS_CTA) {
        const int row = rowbase + tid;
        const int bi  = rowtab[tid];
        const float4* xp = (const float4*)(xs + tid * XSTRIDE);
        float ls = 0.f;
        {
            const float4* ep = (const float4*)(g_et + (size_t)bi * D);
            float4* qp = (float4*)(out + OFF_QUANT + (size_t)row * D);
            #pragma unroll
            for (int i = 0; i < 16; i++) {
                float4 e = ep[i], xv = xp[i];
                qp[i] = e;
                float a0 = e.x - xv.x, a1 = e.y - xv.y;
                float a2 = e.z - xv.z, a3 = e.w - xv.w;
                ls = fmaf(a0, a0, ls); ls = fmaf(a1, a1, ls);
                ls = fmaf(a2, a2, ls); ls = fmaf(a3, a3, ls);
            }
        }
        #pragma unroll
        for (int off = 16; off > 0; off >>= 1)
            ls += __shfl_xor_sync(0xFFFFFFFF, ls, off);
        if (lane == 0)   // fixed-point warp partial -> smem (deterministic)
            wl[wid] = (long long)__float2ll_rn(ls * 16777216.0f);

        out[OFF_IDX + row] = (float)bi;
        out[OFF_ENC + (size_t)row * K + bi] = 1.0f;
    }
    __syncthreads();

    // tid 0: single fenced g_loss add, then last-CTA-done finalize
    if (tid == 0) {
        long long csum = wl[0] + wl[1] + wl[2] + wl[3];
        atomicAdd(&g_loss, (unsigned long long)csum);
        __threadfence();
        unsigned int old = atomicInc(&g_done, NBLK - 1);
        if (old == NBLK - 1) {
            unsigned long long tot = atomicAdd(&g_loss, 0ull);
            out[OFF_LOSS] = (float)((double)tot
                          / (16777216.0 * (double)N_ROWS * (double)D));
        }
    }
}

extern "C" void kernel_launch(void* const* d_in, const int* in_sizes, int n_in,
                              void* d_out, int out_size) {
    const float* x   = (const float*)d_in[0];   // [8,4096,64]
    const float* emb = (const float*)d_in[1];   // [64,1024]
    float* out = (float*)d_out;

    cudaFuncSetAttribute(vq_mma, cudaFuncAttributeMaxDynamicSharedMemorySize,
                         SMEM_SZ);
    prep_all<<<16, 256>>>(emb);
    vq_mma<<<NBLK, NTHR, SMEM_SZ>>>(x, out);
}

// round 17
// speedup vs baseline: 1.3867x; 1.0940x over previous
#include <cuda_runtime.h>
#include <cuda_fp16.h>
#include <cstdint>

#define N_ROWS 32768
#define D      64
#define K      1024
#define NTHR   256                     // 8 warps per CTA
#define ROWS_CTA 128
#define NBLK   (N_ROWS / ROWS_CTA)     // 256 CTAs (2/SM -> one wave)
#define NCH    64
#define NCHUNK (K / NCH)               // 16

#define OFF_QUANT 0
#define OFF_ENC   ((size_t)N_ROWS * D)
#define OFF_IDX   (OFF_ENC + (size_t)N_ROWS * K)
#define OFF_LOSS  (OFF_IDX + (size_t)N_ROWS)

// smem (floats): esq[1024] | buf0[3072] | buf1[3072] | xtile[128*68] | tab[128] | wl[16]
#define SMF_ESQ  0
#define SMF_BUF  1024
#define SMF_X    (1024 + 6144)
#define XSTRIDE  68
#define SMF_TAB  (SMF_X + 128 * XSTRIDE)
#define SMF_WL   (SMF_TAB + 128)
#define SMEM_SZ  ((SMF_WL + 16) * 4)             // 64064 B -> 2 CTAs/SM

// Packed per-chunk B block (12KB each, 16 chunks):
//   u4[  0..255]  hi ks0|ks1   [nt(8)][lane(32)] -> uint4
//   u4[256..511]  hi ks2|ks3
//   u2[1024..1279] esq hi (ks4 pseudo-dim)   (byte 8192)
//   u2[1280..1535] esq lo                    (byte 10240)
__device__ uint4 g_bpk[NCHUNK * 768];
__device__ float g_et [K * D];           // exact emb^T [k][d]
__device__ float g_esq[K];
__device__ unsigned long long g_loss;
__device__ unsigned int g_done;          // wraps to 0 each launch (atomicInc)

__device__ __forceinline__ uint32_t smem_u32(const void* p) {
    uint32_t a;
    asm("{ .reg .u64 t; cvta.to.shared.u64 t, %1; cvt.u32.u64 %0, t; }"
        : "=r"(a) : "l"(p));
    return a;
}
__device__ __forceinline__ uint32_t packh2(float a, float b) {
    __half2 h = __floats2half2_rn(a, b);   // a -> low half (smaller index)
    return *(uint32_t*)&h;
}

#define CP16(dst, src) asm volatile( \
    "cp.async.cg.shared.global [%0], [%1], 16;" :: "r"(dst), "l"(src) : "memory")
#define CP_COMMIT() asm volatile("cp.async.commit_group;" ::: "memory")
#define CP_WAIT0()  asm volatile("cp.async.wait_group 0;" ::: "memory")

#define LDS64(r0, r1, addr) asm volatile( \
    "ld.shared.v2.b32 {%0,%1}, [%2];" : "=r"(r0), "=r"(r1) : "r"(addr))
#define LDS128(r0, r1, r2, r3, addr) asm volatile( \
    "ld.shared.v4.b32 {%0,%1,%2,%3}, [%4];" \
    : "=r"(r0), "=r"(r1), "=r"(r2), "=r"(r3) : "r"(addr))

#define MMAF16(Cp, Ap, B0, B1) asm volatile( \
    "mma.sync.aligned.m16n8k16.row.col.f32.f16.f16.f32 " \
    "{%0,%1,%2,%3},{%4,%5,%6,%7},{%8,%9},{%0,%1,%2,%3};" \
    : "+f"((Cp)[0]), "+f"((Cp)[1]), "+f"((Cp)[2]), "+f"((Cp)[3]) \
    : "r"((Ap)[0]), "r"((Ap)[1]), "r"((Ap)[2]), "r"((Ap)[3]), \
      "r"(B0), "r"(B1))

// ---------------- prep (coalesced): e^T, ||e||^2, packed fp16-hi frags -----
// 16 blocks x 256 threads; block b handles codewords [b*64, b*64+64).
__global__ void prep_all(const float* __restrict__ emb) {
    __shared__ float es[64 * 65];        // [d][cw_local], stride 65
    const int tid = threadIdx.x;
    if (blockIdx.x == 0 && tid == 0) g_loss = 0ull;
    const int cwbase = blockIdx.x * 64;

    // coalesced stage: 64-float segments
    #pragma unroll
    for (int i = 0; i < 16; i++) {
        int d = i * 4 + (tid >> 6);
        int j = tid & 63;
        es[d * 65 + j] = emb[d * K + cwbase + j];
    }
    __syncthreads();

    const int lane = tid & 31;
    const int nt   = tid >> 5;           // 0..7 (local n-tile)
    const int c    = blockIdx.x;         // 64cw block index
    const int cwl  = nt * 8 + (lane >> 2);   // local codeword 0..63

    uint4 hi01, hi23;
    #pragma unroll
    for (int ks = 0; ks < 4; ks++) {
        int d0 = ks * 16 + (lane & 3) * 2;
        float v0 = es[(d0    ) * 65 + cwl];
        float v1 = es[(d0 + 1) * 65 + cwl];
        float v2 = es[(d0 + 8) * 65 + cwl];
        float v3 = es[(d0 + 9) * 65 + cwl];
        uint32_t hu0 = packh2(v0, v1), hu1 = packh2(v2, v3);
        if (ks == 0)      { hi01.x = hu0; hi01.y = hu1; }
        else if (ks == 1) { hi01.z = hu0; hi01.w = hu1; }
        else if (ks == 2) { hi23.x = hu0; hi23.y = hu1; }
        else              { hi23.z = hu0; hi23.w = hu1; }
    }
    int slot = c * 768 + nt * 32 + lane;
    g_bpk[slot      ] = hi01;
    g_bpk[slot + 256] = hi23;

    // ks4: esq pseudo-dim (hi+lo split -> exact); lane&3==0 carries data
    {
        uint2 hv = make_uint2(0, 0), lv = make_uint2(0, 0);
        if ((lane & 3) == 0) {
            float esq = 0.f;
            #pragma unroll
            for (int d = 0; d < D; d++) {
                float v = es[d * 65 + cwl];
                esq = fmaf(v, v, esq);
            }
            float eh = __half2float(__float2half_rn(esq));
            hv.x = packh2(eh, 0.f);
            lv.x = packh2(esq - eh, 0.f);
            g_esq[cwbase + cwl] = esq;
        }
        uint2* p2 = (uint2*)g_bpk;
        p2[c * 1536 + 1024 + nt * 32 + lane] = hv;
        p2[c * 1536 + 1280 + nt * 32 + lane] = lv;
    }

    // exact transpose: first 64 threads each own one cw
    if (tid < 64) {
        int cw = cwbase + tid;
        float4* dst = (float4*)(g_et + (size_t)cw * D);
        #pragma unroll
        for (int i = 0; i < 16; i++) {
            dst[i] = make_float4(es[(4 * i    ) * 65 + tid],
                                 es[(4 * i + 1) * 65 + tid],
                                 es[(4 * i + 2) * 65 + tid],
                                 es[(4 * i + 3) * 65 + tid]);
        }
    }
}

// ---------------- staging: 12KB linear copy per chunk ----------------------
__device__ __forceinline__ void stage_chunk(uint32_t bufb, int c, int tid) {
    const char* s = (const char*)(g_bpk + (size_t)c * 768);
    #pragma unroll
    for (int i = 0; i < 3; i++) {
        uint32_t o = (uint32_t)(i * NTHR + tid) * 16;
        CP16(bufb + o, s + o);
    }
    CP_COMMIT();
}

__device__ __forceinline__ bool sless(float s, int i, float S, int I) {
    return (s < S) || (s == S && i < I);
}

// exact fp32 score of codeword k against x row in smem
__device__ __forceinline__ float exact_score(const float4* __restrict__ xp,
                                             int k, const float* esq_s) {
    const float4* ep = (const float4*)(g_et + (size_t)k * D);
    float d0 = 0.f;
    #pragma unroll
    for (int i = 0; i < 16; i++) {
        float4 xv = xp[i], ev = ep[i];
        d0 = fmaf(xv.x, ev.x, d0); d0 = fmaf(xv.y, ev.y, d0);
        d0 = fmaf(xv.z, ev.z, d0); d0 = fmaf(xv.w, ev.w, d0);
    }
    return fmaf(-2.f, d0, esq_s[k]);
}

// ---------------- main ------------------------------------------------------
__global__ __launch_bounds__(NTHR, 2) void vq_mma(const float* __restrict__ x,
                                                  float* __restrict__ out) {
    extern __shared__ __align__(16) float smem[];
    const uint32_t smb = smem_u32(smem);
    float* esq_s = smem + SMF_ESQ;
    float* xs    = smem + SMF_X;
    const int tid  = threadIdx.x;
    const int wid  = tid >> 5, lane = tid & 31;
    const int r0   = lane >> 2, c0 = lane & 3;
    const int rowbase = blockIdx.x * ROWS_CTA;

    stage_chunk(smb + SMF_BUF * 4, 0, tid);

    #pragma unroll
    for (int i = 0; i < K / NTHR; i++)
        esq_s[i * NTHR + tid] = g_esq[i * NTHR + tid];

    // stage x tile (raw floats, stride 68 => conflict-free row reads)
    {
        const float4* xg = (const float4*)(x + (size_t)rowbase * D);
        #pragma unroll
        for (int i = 0; i < 8; i++) {
            int idx = i * NTHR + tid;
            int r = idx >> 4, d4 = idx & 15;
            *(float4*)(xs + r * XSTRIDE + d4 * 4) = xg[idx];
        }
    }
    __syncthreads();

    // A fragments: y = -2x, split y = y0 + y1 (fp16); +ks4 pseudo-dim (y=1).
    uint32_t ay0[20], ay1[16];
    #pragma unroll
    for (int ks = 0; ks < 4; ks++)
        #pragma unroll
        for (int p = 0; p < 4; p++) {
            int r = wid * 16 + r0 + (p & 1) * 8;
            int d = ks * 16 + c0 * 2 + (p >> 1) * 8;
            float va = -2.f * xs[r * XSTRIDE + d];
            float vb = -2.f * xs[r * XSTRIDE + d + 1];
            float ha = __half2float(__float2half_rn(va));
            float hb = __half2float(__float2half_rn(vb));
            ay0[ks * 4 + p] = packh2(ha, hb);
            ay1[ks * 4 + p] = packh2(va - ha, vb - hb);
        }
    {
        uint32_t one = (c0 == 0) ? packh2(1.f, 0.f) : 0u;
        ay0[16] = one; ay0[17] = one; ay0[18] = 0u; ay0[19] = 0u;
    }

    // per-slot approx top-2; slot 0 = row r0, slot 1 = row r0+8
    float s1[2], s2[2];
    int   i1[2], i2[2];
    #pragma unroll
    for (int s = 0; s < 2; s++) { s1[s] = s2[s] = 3.4e38f; i1[s] = i2[s] = 0; }

    #pragma unroll 1
    for (int c = 0; c < NCHUNK; c++) {
        CP_WAIT0();
        __syncthreads();   // buf[c] visible; prior reads of other buf done
        if (c + 1 < NCHUNK)
            stage_chunk(smb + (SMF_BUF + ((c + 1) & 1) * 3072) * 4, c + 1, tid);

        // encodings zero-fill for this chunk's 64 columns
        {
            float4 z = make_float4(0.f, 0.f, 0.f, 0.f);
            float* enc = out + OFF_ENC + (size_t)rowbase * K + (size_t)c * NCH;
            #pragma unroll
            for (int j = 0; j < 8; j++) {
                int idx = j * NTHR + tid;
                *(float4*)(enc + (size_t)(idx >> 4) * K + (idx & 15) * 4) = z;
            }
        }

        const uint32_t bufb = smb + (SMF_BUF + (c & 1) * 3072) * 4;

        // nt pairs: two independent accumulator chains
        #pragma unroll
        for (int nt = 0; nt < 8; nt += 2) {
            uint32_t Ah01[4], Ah23[4], Ah4[2], Al4[2];
            uint32_t Bh01[4], Bh23[4], Bh4[2], Bl4[2];
            {
                uint32_t a16 = bufb + (uint32_t)(((nt    ) * 32 + lane) * 16);
                uint32_t b16 = bufb + (uint32_t)(((nt + 1) * 32 + lane) * 16);
                uint32_t a8  = bufb + (uint32_t)(((nt    ) * 32 + lane) * 8);
                uint32_t b8  = bufb + (uint32_t)(((nt + 1) * 32 + lane) * 8);
                LDS128(Ah01[0], Ah01[1], Ah01[2], Ah01[3], a16);
                LDS128(Bh01[0], Bh01[1], Bh01[2], Bh01[3], b16);
                LDS128(Ah23[0], Ah23[1], Ah23[2], Ah23[3], a16 + 4096);
                LDS128(Bh23[0], Bh23[1], Bh23[2], Bh23[3], b16 + 4096);
                LDS64(Ah4[0], Ah4[1], a8 + 8192);
                LDS64(Bh4[0], Bh4[1], b8 + 8192);
                LDS64(Al4[0], Al4[1], a8 + 10240);
                LDS64(Bl4[0], Bl4[1], b8 + 10240);
            }
            float C0[4] = {0.f, 0.f, 0.f, 0.f};
            float C1[4] = {0.f, 0.f, 0.f, 0.f};
            MMAF16(C0, ay0 + 0,  Ah01[0], Ah01[1]);   // ks0
            MMAF16(C1, ay0 + 0,  Bh01[0], Bh01[1]);
            MMAF16(C0, ay1 + 0,  Ah01[0], Ah01[1]);
            MMAF16(C1, ay1 + 0,  Bh01[0], Bh01[1]);
            MMAF16(C0, ay0 + 4,  Ah01[2], Ah01[3]);   // ks1
            MMAF16(C1, ay0 + 4,  Bh01[2], Bh01[3]);
            MMAF16(C0, ay1 + 4,  Ah01[2], Ah01[3]);
            MMAF16(C1, ay1 + 4,  Bh01[2], Bh01[3]);
            MMAF16(C0, ay0 + 8,  Ah23[0], Ah23[1]);   // ks2
            MMAF16(C1, ay0 + 8,  Bh23[0], Bh23[1]);
            MMAF16(C0, ay1 + 8,  Ah23[0], Ah23[1]);
            MMAF16(C1, ay1 + 8,  Bh23[0], Bh23[1]);
            MMAF16(C0, ay0 + 12, Ah23[2], Ah23[3]);   // ks3
            MMAF16(C1, ay0 + 12, Bh23[2], Bh23[3]);
            MMAF16(C0, ay1 + 12, Ah23[2], Ah23[3]);
            MMAF16(C1, ay1 + 12, Bh23[2], Bh23[3]);
            MMAF16(C0, ay0 + 16, Ah4[0],  Ah4[1]);    // ks4 esq hi
            MMAF16(C1, ay0 + 16, Bh4[0],  Bh4[1]);
            MMAF16(C0, ay0 + 16, Al4[0],  Al4[1]);    // ks4 esq lo
            MMAF16(C1, ay0 + 16, Bl4[0],  Bl4[1]);

            // approx pair-then-insert top-2 (cols ascending, strict <)
            int cbA = c * NCH + nt * 8 + c0 * 2;
            int cbB = cbA + 8;
            {
                float m = fminf(C0[0], C0[1]);
                int  mc = cbA + ((C0[1] < C0[0]) ? 1 : 0);
                bool p1 = m < s1[0], p2 = m < s2[0];
                s2[0] = p1 ? s1[0] : (p2 ? m : s2[0]);
                i2[0] = p1 ? i1[0] : (p2 ? mc : i2[0]);
                i1[0] = p1 ? mc : i1[0];
                s1[0] = p1 ? m  : s1[0];
            }
            {
                float m = fminf(C0[2], C0[3]);
                int  mc = cbA + ((C0[3] < C0[2]) ? 1 : 0);
                bool p1 = m < s1[1], p2 = m < s2[1];
                s2[1] = p1 ? s1[1] : (p2 ? m : s2[1]);
                i2[1] = p1 ? i1[1] : (p2 ? mc : i2[1]);
                i1[1] = p1 ? mc : i1[1];
                s1[1] = p1 ? m  : s1[1];
            }
            {
                float m = fminf(C1[0], C1[1]);
                int  mc = cbB + ((C1[1] < C1[0]) ? 1 : 0);
                bool p1 = m < s1[0], p2 = m < s2[0];
                s2[0] = p1 ? s1[0] : (p2 ? m : s2[0]);
                i2[0] = p1 ? i1[0] : (p2 ? mc : i2[0]);
                i1[0] = p1 ? mc : i1[0];
                s1[0] = p1 ? m  : s1[0];
            }
            {
                float m = fminf(C1[2], C1[3]);
                int  mc = cbB + ((C1[3] < C1[2]) ? 1 : 0);
                bool p1 = m < s1[1], p2 = m < s2[1];
                s2[1] = p1 ? s1[1] : (p2 ? m : s2[1]);
                i2[1] = p1 ? i1[1] : (p2 ? mc : i2[1]);
                i1[1] = p1 ? mc : i1[1];
                s1[1] = p1 ? m  : s1[1];
            }
        }
    }

    // ---- exact rescue: rescore BOTH per-lane candidates, then quad-merge ----
    int* rowtab = (int*)(smem + SMF_TAB);
    #pragma unroll
    for (int sl = 0; sl < 2; sl++) {
        int r = wid * 16 + sl * 8 + r0;
        const float4* xp = (const float4*)(xs + r * XSTRIDE);
        float ea = exact_score(xp, i1[sl], esq_s);
        float eb = exact_score(xp, i2[sl], esq_s);
        float bs; int bidx;
        if (sless(eb, i2[sl], ea, i1[sl])) { bs = eb; bidx = i2[sl]; }
        else                               { bs = ea; bidx = i1[sl]; }
        #pragma unroll
        for (int off = 1; off <= 2; off <<= 1) {
            float os = __shfl_xor_sync(0xFFFFFFFF, bs, off);
            int   oi = __shfl_xor_sync(0xFFFFFFFF, bidx, off);
            if (sless(os, oi, bs, bidx)) { bs = os; bidx = oi; }
        }
        if (c0 == 0) rowtab[r] = bidx;
    }
    __syncthreads();

    // final per-row epilogue (threads 0..127): outputs + loss
    long long* wl = (long long*)(smem + SMF_WL);
    if (tid < ROWS_CTA) {
        const int row = rowbase + tid;
        const int bi  = rowtab[tid];
        const float4* xp = (const float4*)(xs + tid * XSTRIDE);
        float ls = 0.f;
        {
            const float4* ep = (const float4*)(g_et + (size_t)bi * D);
            float4* qp = (float4*)(out + OFF_QUANT + (size_t)row * D);
            #pragma unroll
            for (int i = 0; i < 16; i++) {
                float4 e = ep[i], xv = xp[i];
                qp[i] = e;
                float a0 = e.x - xv.x, a1 = e.y - xv.y;
                float a2 = e.z - xv.z, a3 = e.w - xv.w;
                ls = fmaf(a0, a0, ls); ls = fmaf(a1, a1, ls);
                ls = fmaf(a2, a2, ls); ls = fmaf(a3, a3, ls);
            }
        }
        #pragma unroll
        for (int off = 16; off > 0; off >>= 1)
            ls += __shfl_xor_sync(0xFFFFFFFF, ls, off);
        if (lane == 0)   // fixed-point warp partial -> smem (deterministic)
            wl[wid] = (long long)__float2ll_rn(ls * 16777216.0f);

        out[OFF_IDX + row] = (float)bi;
        out[OFF_ENC + (size_t)row * K + bi] = 1.0f;
    }
    __syncthreads();

    // tid 0: single fenced g_loss add, then last-CTA-done finalize
    if (tid == 0) {
        long long csum = wl[0] + wl[1] + wl[2] + wl[3];
        atomicAdd(&g_loss, (unsigned long long)csum);
        __threadfence();
        unsigned int old = atomicInc(&g_done, NBLK - 1);
        if (old == NBLK - 1) {
            unsigned long long tot = atomicAdd(&g_loss, 0ull);
            out[OFF_LOSS] = (float)((double)tot
                          / (16777216.0 * (double)N_ROWS * (double)D));
        }
    }
}

extern "C" void kernel_launch(void* const* d_in, const int* in_sizes, int n_in,
                              void* d_out, int out_size) {
    const float* x   = (const float*)d_in[0];   // [8,4096,64]
    const float* emb = (const float*)d_in[1];   // [64,1024]
    float* out = (float*)d_out;

    cudaFuncSetAttribute(vq_mma, cudaFuncAttributeMaxDynamicSharedMemorySize,
                         SMEM_SZ);
    prep_all<<<16, 256>>>(emb);
    vq_mma<<<NBLK, NTHR, SMEM_SZ>>>(x, out);
}